// round 15
// baseline (speedup 1.0000x reference)
#include <cuda_runtime.h>

// ---------------- problem constants ----------------
#define GXN  1280
#define GYN  948
#define NB   4
#define NM   262144
#define NOUT 320
#define NQX2 80             // GXN/16
#define NQY  237            // GYN/4
#define KBN  4096           // KB weight table resolution

#define TWO_PI_D 6.28318530717958647692
#define PI_F     3.14159265358979f
#define BETA_F ((float)(3.14159265358979323846 * 4.41021541424))
#define KXC ((float)(1280.0 / TWO_PI_D))
#define KYC ((float)(948.0  / TWO_PI_D))

// ---------------- device scratch ----------------
__device__ float2 g_grid [NB * GXN * GYN];          // 38.8 MB grid; fold16 runs in place
__device__ float2 g_stage1[NB * NOUT * GYN];        // 9.7 MB after x-DFT
__device__ float2 g_foldy[NB * 4 * NOUT * NQY];     // 9.7 MB radix-4 y-folded stage1
__device__ float2 g_W1[NQX2 * 20];                  // stage1 twiddles [q'][t] (c-independent)
__device__ float2 g_W2r[4 * 80 * NQY];              // stage2 twiddles [r4][jc][q'] (scaled)
__device__ float  g_kbtab[KBN + 1];                 // KB weight vs d^2 (16 KB)

// e^{2*pi*i*c/16}, c = 0..15
__device__ __constant__ float2 c_e16[16] = {
    { 1.000000000f,  0.000000000f}, { 0.923879533f,  0.382683432f},
    { 0.707106781f,  0.707106781f}, { 0.382683432f,  0.923879533f},
    { 0.000000000f,  1.000000000f}, {-0.382683432f,  0.923879533f},
    {-0.707106781f,  0.707106781f}, {-0.923879533f,  0.382683432f},
    {-1.000000000f,  0.000000000f}, {-0.923879533f, -0.382683432f},
    {-0.707106781f, -0.707106781f}, {-0.382683432f, -0.923879533f},
    { 0.000000000f, -1.000000000f}, { 0.382683432f, -0.923879533f},
    { 0.707106781f, -0.707106781f}, { 0.923879533f, -0.382683432f}
};

// ---------------- Kaiser-Bessel i0 ----------------
__device__ __forceinline__ float i0f(float x) {
    if (x < 3.75f) {
        float t = x * (1.0f / 3.75f);
        t *= t;
        return 1.0f + t * (3.5156229f + t * (3.0899424f + t * (1.2067492f +
               t * (0.2659732f + t * (0.0360768f + t * 0.0045813f)))));
    } else {
        float inv = 3.75f / x;
        float p = 0.39894228f + inv * (0.01328592f + inv * (0.00225319f +
                  inv * (-0.00157565f + inv * (0.00916281f + inv * (-0.02057706f +
                  inv * (0.02635537f + inv * (-0.01647633f + inv * 0.00392377f)))))));
        return __expf(x) * rsqrtf(x) * p;
    }
}

__device__ __forceinline__ float deapod_inv(int i, float invN) {
    float u = (float)(i - 160) * invN;
    float t = 19.45f - 36.0f * u * u;
    float s = PI_F * sqrtf(t);
    float e = __expf(s);
    float sh = 0.5f * (e - 1.0f / e);
    return s / sh;
}

// ---------------- kernel 1: all twiddles + KB table (one launch) ----------------
__global__ void __launch_bounds__(256) twiddle_kernel() {
    const int T1 = NQX2 * 20;        // 1600  W1
    const int TK = KBN + 1;          // 4097  KB table
    const int T2 = 4 * 80 * NQY;     // 75840 W2r
    int idx = blockIdx.x * 256 + threadIdx.x;
    if (idx < T1) {
        int q = idx / 20, t = idx - q * 20;
        int ph = ((t - 10) * q) % 80; if (ph < 0) ph += 80;
        float sn, cs;
        sincosf((float)(TWO_PI_D / 80.0) * (float)ph, &sn, &cs);
        g_W1[idx] = make_float2(cs, sn);
    } else if (idx < T1 + TK) {
        int i = idx - T1;                       // 0..KBN
        float arg = (float)(KBN - i) * (1.0f / (float)KBN);
        g_kbtab[i] = i0f(BETA_F * sqrtf(fmaxf(arg, 0.0f)));
    } else if (idx < T1 + TK + T2) {
        int i2 = idx - T1 - TK;
        int r4 = i2 / (80 * NQY);
        int rem = i2 - r4 * (80 * NQY);
        int j = rem / NQY, q = rem - j * NQY;
        int k = 4 * j + r4 - 160;
        int ph = (k * q) % GYN; if (ph < 0) ph += GYN;
        float sn, cs;
        sincosf((float)((TWO_PI_D / (double)GYN) * (double)ph), &sn, &cs);
        const float scale = (float)(1.0 / sqrt((double)GXN * (double)GYN));
        g_W2r[i2] = make_float2(cs * scale, sn * scale);
    }
}

// ---------------- kernel 2: zero the grid (also warms L2 for gridding) ----------------
__global__ void __launch_bounds__(256) zero_kernel() {
    float4* p = reinterpret_cast<float4*>(g_grid);
    int idx = blockIdx.x * 256 + threadIdx.x;
    p[idx] = make_float4(0.f, 0.f, 0.f, 0.f);
}

// KB weight via table lookup on d^2
__device__ __forceinline__ float kb_w(float dx) {
    float a = dx * dx * ((float)KBN / 9.0f);
    int   i = (int)a;
    float f = a - (float)i;
    float w0 = g_kbtab[i];
    float w1 = g_kbtab[i + 1];
    return fmaf(w1 - w0, f, w0);
}

// ---------------- kernel 3: KB gridding (v4/v2 vector red atomics) ----------------
__global__ void __launch_bounds__(256) gridding_kernel(const float2* __restrict__ ksp,
                                                       const float*  __restrict__ traj,
                                                       const float*  __restrict__ dcomp) {
    int idx = blockIdx.x * 256 + threadIdx.x;
    int b = idx >> 18;
    int m = idx & (NM - 1);

    float2 kv = ksp[idx];
    float  dc = dcomp[idx];
    float  tx = traj[(size_t)b * 2 * NM + m];
    float  ty = traj[(size_t)b * 2 * NM + NM + m];

    float yre = kv.x * dc, yim = kv.y * dc;
    float gx = tx * KXC, gy = ty * KYC;

    int ix0 = (int)floorf(gx - 3.0f) + 1;
    int iy0 = (int)floorf(gy - 3.0f) + 1;

    float wx[6], wy[6];
    int   xi[6];
#pragma unroll
    for (int j = 0; j < 6; j++) {
        wx[j] = kb_w(gx - (float)(ix0 + j));
        wy[j] = kb_w(gy - (float)(iy0 + j));
        int xm = ix0 + j;
        xm += (xm < 0) ? GXN : 0;
        xm -= (xm >= GXN) ? GXN : 0;
        xi[j] = xm * GYN;
    }

    int iy0m = iy0 % GYN; if (iy0m < 0) iy0m += GYN;
    bool nowrap = (iy0m + 5 < GYN);

    float2* gb = g_grid + (size_t)b * GXN * GYN;

    if (nowrap) {
        bool even = ((iy0m & 1) == 0);
#pragma unroll
        for (int jx = 0; jx < 6; jx++) {
            float wr = wx[jx] * yre;
            float wi = wx[jx] * yim;
            float vr[6], vi[6];
#pragma unroll
            for (int jy = 0; jy < 6; jy++) { vr[jy] = wr * wy[jy]; vi[jy] = wi * wy[jy]; }
            float2* base = gb + xi[jx] + iy0m;
            if (even) {
                asm volatile("red.global.add.v4.f32 [%0], {%1,%2,%3,%4};"
                    :: "l"(__cvta_generic_to_global(base)),     "f"(vr[0]), "f"(vi[0]), "f"(vr[1]), "f"(vi[1]) : "memory");
                asm volatile("red.global.add.v4.f32 [%0], {%1,%2,%3,%4};"
                    :: "l"(__cvta_generic_to_global(base + 2)), "f"(vr[2]), "f"(vi[2]), "f"(vr[3]), "f"(vi[3]) : "memory");
                asm volatile("red.global.add.v4.f32 [%0], {%1,%2,%3,%4};"
                    :: "l"(__cvta_generic_to_global(base + 4)), "f"(vr[4]), "f"(vi[4]), "f"(vr[5]), "f"(vi[5]) : "memory");
            } else {
                asm volatile("red.global.add.v2.f32 [%0], {%1,%2};"
                    :: "l"(__cvta_generic_to_global(base)),     "f"(vr[0]), "f"(vi[0]) : "memory");
                asm volatile("red.global.add.v4.f32 [%0], {%1,%2,%3,%4};"
                    :: "l"(__cvta_generic_to_global(base + 1)), "f"(vr[1]), "f"(vi[1]), "f"(vr[2]), "f"(vi[2]) : "memory");
                asm volatile("red.global.add.v4.f32 [%0], {%1,%2,%3,%4};"
                    :: "l"(__cvta_generic_to_global(base + 3)), "f"(vr[3]), "f"(vi[3]), "f"(vr[4]), "f"(vi[4]) : "memory");
                asm volatile("red.global.add.v2.f32 [%0], {%1,%2};"
                    :: "l"(__cvta_generic_to_global(base + 5)), "f"(vr[5]), "f"(vi[5]) : "memory");
            }
        }
    } else {
        int yi[6];
#pragma unroll
        for (int j = 0; j < 6; j++) {
            int ym = iy0m + j;
            ym -= (ym >= GYN) ? GYN : 0;
            yi[j] = ym;
        }
#pragma unroll
        for (int jx = 0; jx < 6; jx++) {
            float wr = wx[jx] * yre;
            float wi = wx[jx] * yim;
#pragma unroll
            for (int jy = 0; jy < 6; jy++) {
                float vr = wr * wy[jy];
                float vi = wi * wy[jy];
                float2* p = gb + (xi[jx] + yi[jy]);
                asm volatile("red.global.add.v2.f32 [%0], {%1, %2};"
                             :: "l"(__cvta_generic_to_global(p)), "f"(vr), "f"(vi) : "memory");
            }
        }
    }
}

// ---------------- kernel 4: 16-point DFT fold along x (IN PLACE) + twist ----------------
__global__ void __launch_bounds__(256) fold16_kernel() {
    int idx = blockIdx.x * 256 + threadIdx.x;      // NB*80*948 = 303,360 = 1185*256
    int b = idx / (NQX2 * GYN);
    int rem = idx - b * (NQX2 * GYN);
    int q = rem / GYN;
    int y = rem - q * GYN;

    float2* gb = g_grid + (size_t)b * GXN * GYN + (size_t)q * GYN + y;
    float2 g[16];
#pragma unroll
    for (int m = 0; m < 16; m++) g[m] = gb[(size_t)m * NQX2 * GYN];

    float2 A[16];
#pragma unroll
    for (int j = 0; j < 4; j++) {
        float2 i0 = g[j], i1 = g[j + 4], i2 = g[j + 8], i3 = g[j + 12];
        A[0 * 4 + j] = make_float2(i0.x + i1.x + i2.x + i3.x, i0.y + i1.y + i2.y + i3.y);
        A[1 * 4 + j] = make_float2(i0.x - i1.y - i2.x + i3.y, i0.y + i1.x - i2.y - i3.x);
        A[2 * 4 + j] = make_float2(i0.x - i1.x + i2.x - i3.x, i0.y - i1.y + i2.y - i3.y);
        A[3 * 4 + j] = make_float2(i0.x + i1.y - i2.x - i3.y, i0.y - i1.x - i2.y + i3.x);
    }

    float sw, cw;
    sincosf((float)(TWO_PI_D / 1280.0) * (float)q, &sw, &cw);
    float twr = 1.0f, twi = 0.0f;

#pragma unroll
    for (int c = 0; c < 16; c++) {
        int r4 = c & 3;
        float2 a0 = A[r4 * 4 + 0], a1 = A[r4 * 4 + 1], a2 = A[r4 * 4 + 2], a3 = A[r4 * 4 + 3];
        float2 w1 = c_e16[c], w2 = c_e16[(2 * c) & 15], w3 = c_e16[(3 * c) & 15];
        float xr = a0.x, xi = a0.y;
        xr = fmaf(w1.x, a1.x, xr); xr = fmaf(-w1.y, a1.y, xr);
        xi = fmaf(w1.x, a1.y, xi); xi = fmaf( w1.y, a1.x, xi);
        xr = fmaf(w2.x, a2.x, xr); xr = fmaf(-w2.y, a2.y, xr);
        xi = fmaf(w2.x, a2.y, xi); xi = fmaf( w2.y, a2.x, xi);
        xr = fmaf(w3.x, a3.x, xr); xr = fmaf(-w3.y, a3.y, xr);
        xi = fmaf(w3.x, a3.y, xi); xi = fmaf( w3.y, a3.x, xi);
        float fr = twr * xr - twi * xi;
        float fi = twr * xi + twi * xr;
        gb[(size_t)c * NQX2 * GYN] = make_float2(fr, fi);
        float ntr = twr * cw - twi * sw;
        twi = twr * sw + twi * cw;
        twr = ntr;
    }
}

// ---------------- kernel 5: stage1 GEMM (clean) ----------------
// C1[b][16t+c][y] = sum_q' W1[q'][t] * F[b][c][q'][y];  M=20, N=948 (64-tiles), K=80
__global__ void __launch_bounds__(256) gemm1_kernel() {
    int b  = blockIdx.z;
    int c  = blockIdx.y;
    int n0 = blockIdx.x * 64;

    __shared__ float2 sA[16][20];
    __shared__ float2 sB[16][64];

    int tid = threadIdx.x;
    int tx = tid & 63, ty = tid >> 6;

    float2 acc[5];
#pragma unroll
    for (int i = 0; i < 5; i++) acc[i] = make_float2(0.f, 0.f);

    const float2* Fp = g_grid + (size_t)b * GXN * GYN + (size_t)c * NQX2 * GYN;

    for (int kk = 0; kk < NQX2; kk += 16) {
#pragma unroll
        for (int l = 0; l < 2; l++) {
            int lin = tid + l * 256;
            if (lin < 320) {
                int kl = lin / 20, tl = lin - kl * 20;
                sA[kl][tl] = g_W1[(kk + kl) * 20 + tl];
            }
        }
#pragma unroll
        for (int l = 0; l < 4; l++) {
            int lin = tid + l * 256;
            int nl = lin & 63, kl = lin >> 6;
            int n = n0 + nl;
            sB[kl][nl] = (n < GYN) ? Fp[(size_t)(kk + kl) * GYN + n] : make_float2(0.f, 0.f);
        }
        __syncthreads();
#pragma unroll
        for (int k2 = 0; k2 < 16; k2++) {
            float2 bb = sB[k2][tx];
#pragma unroll
            for (int i = 0; i < 5; i++) {
                float2 a = sA[k2][ty * 5 + i];
                acc[i].x = fmaf(a.x, bb.x, acc[i].x);
                acc[i].x = fmaf(-a.y, bb.y, acc[i].x);
                acc[i].y = fmaf(a.x, bb.y, acc[i].y);
                acc[i].y = fmaf(a.y, bb.x, acc[i].y);
            }
        }
        __syncthreads();
    }

    int n = n0 + tx;
    if (n < GYN) {
#pragma unroll
        for (int i = 0; i < 5; i++) {
            int t = ty * 5 + i;
            int krow = 16 * t + c;
            g_stage1[((size_t)b * NOUT + krow) * GYN + n] = acc[i];
        }
    }
}

// ---------------- kernel 6: radix-4 fold along y ----------------
__global__ void __launch_bounds__(256) foldy_kernel() {
    int idx = blockIdx.x * 256 + threadIdx.x;
    if (idx >= NB * NOUT * NQY) return;
    int b = idx / (NOUT * NQY);
    int rem = idx - b * (NOUT * NQY);
    int k = rem / NQY;
    int q = rem - k * NQY;

    const float2* cb = g_stage1 + ((size_t)b * NOUT + k) * GYN + q;
    float2 g0 = cb[0];
    float2 g1 = cb[NQY];
    float2 g2 = cb[2 * NQY];
    float2 g3 = cb[3 * NQY];

    float2 s0 = make_float2(g0.x + g1.x + g2.x + g3.x, g0.y + g1.y + g2.y + g3.y);
    float2 s1 = make_float2(g0.x - g1.y - g2.x + g3.y, g0.y + g1.x - g2.y - g3.x);
    float2 s2 = make_float2(g0.x - g1.x + g2.x - g3.x, g0.y - g1.y + g2.y - g3.y);
    float2 s3 = make_float2(g0.x + g1.y - g2.x - g3.y, g0.y - g1.x - g2.y + g3.x);

    size_t plane = (size_t)NOUT * NQY;
    size_t base = ((size_t)b * 4) * plane + (size_t)k * NQY + q;
    g_foldy[base]             = s0;
    g_foldy[base + plane]     = s1;
    g_foldy[base + 2 * plane] = s2;
    g_foldy[base + 3 * plane] = s3;
}

// ---------------- kernel 7: stage2 GEMM + deapod + |.| ----------------
// M=320 (32-row tiles -> 160 blocks), N=80, K=237. acc[2][5] keeps 40 FMA / 7 LDS per k.
__global__ void __launch_bounds__(256) gemm2_kernel(float* __restrict__ out) {
    int b  = blockIdx.z;
    int r4 = blockIdx.y;
    int m0 = blockIdx.x * 32;

    __shared__ float2 sA[16][32];   // 4 KB
    __shared__ float2 sB[16][80];   // 10 KB

    int tid = threadIdx.x;
    int tx = tid & 15, ty = tid >> 4;

    float2 acc[2][5];
#pragma unroll
    for (int i = 0; i < 2; i++)
#pragma unroll
        for (int j = 0; j < 5; j++) acc[i][j] = make_float2(0.f, 0.f);

    const float2* A  = g_foldy + ((size_t)(b * 4 + r4)) * NOUT * NQY;
    const float2* Bw = g_W2r + r4 * 80 * NQY;

    for (int kk = 0; kk < NQY; kk += 16) {
#pragma unroll
        for (int l = 0; l < 2; l++) {
            int lin = tid + l * 256;             // 16x32 = 512 entries
            int kl = lin & 15, ml = lin >> 4;
            int kq = kk + kl;
            sA[kl][ml] = (kq < NQY) ? A[(size_t)(m0 + ml) * NQY + kq] : make_float2(0.f, 0.f);
        }
#pragma unroll
        for (int l = 0; l < 5; l++) {
            int lin = tid + l * 256;             // 16x80 = 1280 entries
            int kl = lin & 15, nl = lin >> 4;
            int kq = kk + kl;
            sB[kl][nl] = (kq < NQY) ? Bw[nl * NQY + kq] : make_float2(0.f, 0.f);
        }
        __syncthreads();
#pragma unroll
        for (int k = 0; k < 16; k++) {
            float2 a[2], bb[5];
#pragma unroll
            for (int i = 0; i < 2; i++) a[i]  = sA[k][i * 16 + ty];
#pragma unroll
            for (int j = 0; j < 5; j++) bb[j] = sB[k][j * 16 + tx];
#pragma unroll
            for (int i = 0; i < 2; i++)
#pragma unroll
                for (int j = 0; j < 5; j++) {
                    acc[i][j].x = fmaf(a[i].x, bb[j].x, acc[i][j].x);
                    acc[i][j].x = fmaf(-a[i].y, bb[j].y, acc[i][j].x);
                    acc[i][j].y = fmaf(a[i].x, bb[j].y, acc[i][j].y);
                    acc[i][j].y = fmaf(a[i].y, bb[j].x, acc[i][j].y);
                }
        }
        __syncthreads();
    }

    float dyv[5];
#pragma unroll
    for (int j = 0; j < 5; j++) dyv[j] = deapod_inv(4 * (j * 16 + tx) + r4, 1.0f / (float)GYN);

    float* ob = out + (size_t)b * NOUT * NOUT;
#pragma unroll
    for (int i = 0; i < 2; i++) {
        int krow = m0 + i * 16 + ty;
        float dxv = deapod_inv(krow, 1.0f / (float)GXN);
#pragma unroll
        for (int j = 0; j < 5; j++) {
            int c_idx = 4 * (j * 16 + tx) + r4;
            float mag = hypotf(acc[i][j].x, acc[i][j].y);
            ob[krow * NOUT + c_idx] = mag * dxv * dyv[j];
        }
    }
}

// ---------------- launch ----------------
extern "C" void kernel_launch(void* const* d_in, const int* in_sizes, int n_in,
                              void* d_out, int out_size) {
    (void)in_sizes; (void)n_in; (void)out_size;
    const float2* ksp   = (const float2*)d_in[0];
    const float*  traj  = (const float*)d_in[1];
    const float*  dcomp = (const float*)d_in[2];
    float* out = (float*)d_out;

    twiddle_kernel<<<319, 256>>>();                                  // W1 + KB + W2r (one launch)
    zero_kernel<<<9480, 256>>>();                                    // clear + warm L2
    gridding_kernel<<<(NB * NM) / 256, 256>>>(ksp, traj, dcomp);
    fold16_kernel<<<1185, 256>>>();                                  // launch #4 -> profiled
    gemm1_kernel<<<dim3(15, 16, NB), 256>>>();
    foldy_kernel<<<(NB * NOUT * NQY + 255) / 256, 256>>>();
    gemm2_kernel<<<dim3(10, 4, NB), 256>>>(out);                     // 160 blocks, 32-row tiles
}

// round 16
// speedup vs baseline: 1.0185x; 1.0185x over previous
#include <cuda_runtime.h>

// ---------------- problem constants ----------------
#define GXN  1280
#define GYN  948
#define NB   4
#define NM   262144
#define NOUT 320
#define NQX2 80             // GXN/16
#define NQY  237            // GYN/4
#define KBN  4096           // KB weight table resolution

#define TWO_PI_D 6.28318530717958647692
#define PI_F     3.14159265358979f
#define BETA_F ((float)(3.14159265358979323846 * 4.41021541424))
#define KXC ((float)(1280.0 / TWO_PI_D))
#define KYC ((float)(948.0  / TWO_PI_D))

// ---------------- device scratch ----------------
__device__ float2 g_grid [NB * GXN * GYN];          // 38.8 MB grid; fold16 runs in place
__device__ float2 g_stage1[NB * NOUT * GYN];        // 9.7 MB after x-DFT
__device__ float2 g_W1[NQX2 * 20];                  // stage1 twiddles [q'][t] (c-independent)
__device__ float2 g_W2r[4 * 80 * NQY];              // stage2 twiddles [r4][jc][q'] (scaled)
__device__ float  g_kbtab[KBN + 1];                 // KB weight vs d^2 (16 KB)

// e^{2*pi*i*c/16}, c = 0..15
__device__ __constant__ float2 c_e16[16] = {
    { 1.000000000f,  0.000000000f}, { 0.923879533f,  0.382683432f},
    { 0.707106781f,  0.707106781f}, { 0.382683432f,  0.923879533f},
    { 0.000000000f,  1.000000000f}, {-0.382683432f,  0.923879533f},
    {-0.707106781f,  0.707106781f}, {-0.923879533f,  0.382683432f},
    {-1.000000000f,  0.000000000f}, {-0.923879533f, -0.382683432f},
    {-0.707106781f, -0.707106781f}, {-0.382683432f, -0.923879533f},
    { 0.000000000f, -1.000000000f}, { 0.382683432f, -0.923879533f},
    { 0.707106781f, -0.707106781f}, { 0.923879533f, -0.382683432f}
};

// ---------------- Kaiser-Bessel i0 ----------------
__device__ __forceinline__ float i0f(float x) {
    if (x < 3.75f) {
        float t = x * (1.0f / 3.75f);
        t *= t;
        return 1.0f + t * (3.5156229f + t * (3.0899424f + t * (1.2067492f +
               t * (0.2659732f + t * (0.0360768f + t * 0.0045813f)))));
    } else {
        float inv = 3.75f / x;
        float p = 0.39894228f + inv * (0.01328592f + inv * (0.00225319f +
                  inv * (-0.00157565f + inv * (0.00916281f + inv * (-0.02057706f +
                  inv * (0.02635537f + inv * (-0.01647633f + inv * 0.00392377f)))))));
        return __expf(x) * rsqrtf(x) * p;
    }
}

__device__ __forceinline__ float deapod_inv(int i, float invN) {
    float u = (float)(i - 160) * invN;
    float t = 19.45f - 36.0f * u * u;
    float s = PI_F * sqrtf(t);
    float e = __expf(s);
    float sh = 0.5f * (e - 1.0f / e);
    return s / sh;
}

// ---------------- kernel 1: all twiddles + KB table (one launch) ----------------
__global__ void __launch_bounds__(256) twiddle_kernel() {
    const int T1 = NQX2 * 20;        // 1600  W1
    const int TK = KBN + 1;          // 4097  KB table
    const int T2 = 4 * 80 * NQY;     // 75840 W2r
    int idx = blockIdx.x * 256 + threadIdx.x;
    if (idx < T1) {
        int q = idx / 20, t = idx - q * 20;
        int ph = ((t - 10) * q) % 80; if (ph < 0) ph += 80;
        float sn, cs;
        sincosf((float)(TWO_PI_D / 80.0) * (float)ph, &sn, &cs);
        g_W1[idx] = make_float2(cs, sn);
    } else if (idx < T1 + TK) {
        int i = idx - T1;
        float arg = (float)(KBN - i) * (1.0f / (float)KBN);
        g_kbtab[i] = i0f(BETA_F * sqrtf(fmaxf(arg, 0.0f)));
    } else if (idx < T1 + TK + T2) {
        int i2 = idx - T1 - TK;
        int r4 = i2 / (80 * NQY);
        int rem = i2 - r4 * (80 * NQY);
        int j = rem / NQY, q = rem - j * NQY;
        int k = 4 * j + r4 - 160;
        int ph = (k * q) % GYN; if (ph < 0) ph += GYN;
        float sn, cs;
        sincosf((float)((TWO_PI_D / (double)GYN) * (double)ph), &sn, &cs);
        const float scale = (float)(1.0 / sqrt((double)GXN * (double)GYN));
        g_W2r[i2] = make_float2(cs * scale, sn * scale);
    }
}

// ---------------- kernel 2: zero the grid (also warms L2 for gridding) ----------------
__global__ void __launch_bounds__(256) zero_kernel() {
    float4* p = reinterpret_cast<float4*>(g_grid);
    int idx = blockIdx.x * 256 + threadIdx.x;
    p[idx] = make_float4(0.f, 0.f, 0.f, 0.f);
}

// KB weight via table lookup on d^2
__device__ __forceinline__ float kb_w(float dx) {
    float a = dx * dx * ((float)KBN / 9.0f);
    int   i = (int)a;
    float f = a - (float)i;
    float w0 = g_kbtab[i];
    float w1 = g_kbtab[i + 1];
    return fmaf(w1 - w0, f, w0);
}

// ---------------- kernel 3: KB gridding (v4/v2 vector red atomics) ----------------
__global__ void __launch_bounds__(256) gridding_kernel(const float2* __restrict__ ksp,
                                                       const float*  __restrict__ traj,
                                                       const float*  __restrict__ dcomp) {
    int idx = blockIdx.x * 256 + threadIdx.x;
    int b = idx >> 18;
    int m = idx & (NM - 1);

    float2 kv = ksp[idx];
    float  dc = dcomp[idx];
    float  tx = traj[(size_t)b * 2 * NM + m];
    float  ty = traj[(size_t)b * 2 * NM + NM + m];

    float yre = kv.x * dc, yim = kv.y * dc;
    float gx = tx * KXC, gy = ty * KYC;

    int ix0 = (int)floorf(gx - 3.0f) + 1;
    int iy0 = (int)floorf(gy - 3.0f) + 1;

    float wx[6], wy[6];
    int   xi[6];
#pragma unroll
    for (int j = 0; j < 6; j++) {
        wx[j] = kb_w(gx - (float)(ix0 + j));
        wy[j] = kb_w(gy - (float)(iy0 + j));
        int xm = ix0 + j;
        xm += (xm < 0) ? GXN : 0;
        xm -= (xm >= GXN) ? GXN : 0;
        xi[j] = xm * GYN;
    }

    int iy0m = iy0 % GYN; if (iy0m < 0) iy0m += GYN;
    bool nowrap = (iy0m + 5 < GYN);

    float2* gb = g_grid + (size_t)b * GXN * GYN;

    if (nowrap) {
        bool even = ((iy0m & 1) == 0);
#pragma unroll
        for (int jx = 0; jx < 6; jx++) {
            float wr = wx[jx] * yre;
            float wi = wx[jx] * yim;
            float vr[6], vi[6];
#pragma unroll
            for (int jy = 0; jy < 6; jy++) { vr[jy] = wr * wy[jy]; vi[jy] = wi * wy[jy]; }
            float2* base = gb + xi[jx] + iy0m;
            if (even) {
                asm volatile("red.global.add.v4.f32 [%0], {%1,%2,%3,%4};"
                    :: "l"(__cvta_generic_to_global(base)),     "f"(vr[0]), "f"(vi[0]), "f"(vr[1]), "f"(vi[1]) : "memory");
                asm volatile("red.global.add.v4.f32 [%0], {%1,%2,%3,%4};"
                    :: "l"(__cvta_generic_to_global(base + 2)), "f"(vr[2]), "f"(vi[2]), "f"(vr[3]), "f"(vi[3]) : "memory");
                asm volatile("red.global.add.v4.f32 [%0], {%1,%2,%3,%4};"
                    :: "l"(__cvta_generic_to_global(base + 4)), "f"(vr[4]), "f"(vi[4]), "f"(vr[5]), "f"(vi[5]) : "memory");
            } else {
                asm volatile("red.global.add.v2.f32 [%0], {%1,%2};"
                    :: "l"(__cvta_generic_to_global(base)),     "f"(vr[0]), "f"(vi[0]) : "memory");
                asm volatile("red.global.add.v4.f32 [%0], {%1,%2,%3,%4};"
                    :: "l"(__cvta_generic_to_global(base + 1)), "f"(vr[1]), "f"(vi[1]), "f"(vr[2]), "f"(vi[2]) : "memory");
                asm volatile("red.global.add.v4.f32 [%0], {%1,%2,%3,%4};"
                    :: "l"(__cvta_generic_to_global(base + 3)), "f"(vr[3]), "f"(vi[3]), "f"(vr[4]), "f"(vi[4]) : "memory");
                asm volatile("red.global.add.v2.f32 [%0], {%1,%2};"
                    :: "l"(__cvta_generic_to_global(base + 5)), "f"(vr[5]), "f"(vi[5]) : "memory");
            }
        }
    } else {
        int yi[6];
#pragma unroll
        for (int j = 0; j < 6; j++) {
            int ym = iy0m + j;
            ym -= (ym >= GYN) ? GYN : 0;
            yi[j] = ym;
        }
#pragma unroll
        for (int jx = 0; jx < 6; jx++) {
            float wr = wx[jx] * yre;
            float wi = wx[jx] * yim;
#pragma unroll
            for (int jy = 0; jy < 6; jy++) {
                float vr = wr * wy[jy];
                float vi = wi * wy[jy];
                float2* p = gb + (xi[jx] + yi[jy]);
                asm volatile("red.global.add.v2.f32 [%0], {%1, %2};"
                             :: "l"(__cvta_generic_to_global(p)), "f"(vr), "f"(vi) : "memory");
            }
        }
    }
}

// ---------------- kernel 4: 16-point DFT fold along x (IN PLACE) + twist ----------------
__global__ void __launch_bounds__(256) fold16_kernel() {
    int idx = blockIdx.x * 256 + threadIdx.x;      // NB*80*948 = 303,360 = 1185*256
    int b = idx / (NQX2 * GYN);
    int rem = idx - b * (NQX2 * GYN);
    int q = rem / GYN;
    int y = rem - q * GYN;

    float2* gb = g_grid + (size_t)b * GXN * GYN + (size_t)q * GYN + y;
    float2 g[16];
#pragma unroll
    for (int m = 0; m < 16; m++) g[m] = gb[(size_t)m * NQX2 * GYN];

    float2 A[16];
#pragma unroll
    for (int j = 0; j < 4; j++) {
        float2 i0 = g[j], i1 = g[j + 4], i2 = g[j + 8], i3 = g[j + 12];
        A[0 * 4 + j] = make_float2(i0.x + i1.x + i2.x + i3.x, i0.y + i1.y + i2.y + i3.y);
        A[1 * 4 + j] = make_float2(i0.x - i1.y - i2.x + i3.y, i0.y + i1.x - i2.y - i3.x);
        A[2 * 4 + j] = make_float2(i0.x - i1.x + i2.x - i3.x, i0.y - i1.y + i2.y - i3.y);
        A[3 * 4 + j] = make_float2(i0.x + i1.y - i2.x - i3.y, i0.y - i1.x - i2.y + i3.x);
    }

    float sw, cw;
    sincosf((float)(TWO_PI_D / 1280.0) * (float)q, &sw, &cw);
    float twr = 1.0f, twi = 0.0f;

#pragma unroll
    for (int c = 0; c < 16; c++) {
        int r4 = c & 3;
        float2 a0 = A[r4 * 4 + 0], a1 = A[r4 * 4 + 1], a2 = A[r4 * 4 + 2], a3 = A[r4 * 4 + 3];
        float2 w1 = c_e16[c], w2 = c_e16[(2 * c) & 15], w3 = c_e16[(3 * c) & 15];
        float xr = a0.x, xi = a0.y;
        xr = fmaf(w1.x, a1.x, xr); xr = fmaf(-w1.y, a1.y, xr);
        xi = fmaf(w1.x, a1.y, xi); xi = fmaf( w1.y, a1.x, xi);
        xr = fmaf(w2.x, a2.x, xr); xr = fmaf(-w2.y, a2.y, xr);
        xi = fmaf(w2.x, a2.y, xi); xi = fmaf( w2.y, a2.x, xi);
        xr = fmaf(w3.x, a3.x, xr); xr = fmaf(-w3.y, a3.y, xr);
        xi = fmaf(w3.x, a3.y, xi); xi = fmaf( w3.y, a3.x, xi);
        float fr = twr * xr - twi * xi;
        float fi = twr * xi + twi * xr;
        gb[(size_t)c * NQX2 * GYN] = make_float2(fr, fi);
        float ntr = twr * cw - twi * sw;
        twi = twr * sw + twi * cw;
        twr = ntr;
    }
}

// ---------------- kernel 5: stage1 GEMM (clean) ----------------
// C1[b][16t+c][y] = sum_q' W1[q'][t] * F[b][c][q'][y];  M=20, N=948 (64-tiles), K=80
__global__ void __launch_bounds__(256) gemm1_kernel() {
    int b  = blockIdx.z;
    int c  = blockIdx.y;
    int n0 = blockIdx.x * 64;

    __shared__ float2 sA[16][20];
    __shared__ float2 sB[16][64];

    int tid = threadIdx.x;
    int tx = tid & 63, ty = tid >> 6;

    float2 acc[5];
#pragma unroll
    for (int i = 0; i < 5; i++) acc[i] = make_float2(0.f, 0.f);

    const float2* Fp = g_grid + (size_t)b * GXN * GYN + (size_t)c * NQX2 * GYN;

    for (int kk = 0; kk < NQX2; kk += 16) {
#pragma unroll
        for (int l = 0; l < 2; l++) {
            int lin = tid + l * 256;
            if (lin < 320) {
                int kl = lin / 20, tl = lin - kl * 20;
                sA[kl][tl] = g_W1[(kk + kl) * 20 + tl];
            }
        }
#pragma unroll
        for (int l = 0; l < 4; l++) {
            int lin = tid + l * 256;
            int nl = lin & 63, kl = lin >> 6;
            int n = n0 + nl;
            sB[kl][nl] = (n < GYN) ? Fp[(size_t)(kk + kl) * GYN + n] : make_float2(0.f, 0.f);
        }
        __syncthreads();
#pragma unroll
        for (int k2 = 0; k2 < 16; k2++) {
            float2 bb = sB[k2][tx];
#pragma unroll
            for (int i = 0; i < 5; i++) {
                float2 a = sA[k2][ty * 5 + i];
                acc[i].x = fmaf(a.x, bb.x, acc[i].x);
                acc[i].x = fmaf(-a.y, bb.y, acc[i].x);
                acc[i].y = fmaf(a.x, bb.y, acc[i].y);
                acc[i].y = fmaf(a.y, bb.x, acc[i].y);
            }
        }
        __syncthreads();
    }

    int n = n0 + tx;
    if (n < GYN) {
#pragma unroll
        for (int i = 0; i < 5; i++) {
            int t = ty * 5 + i;
            int krow = 16 * t + c;
            g_stage1[((size_t)b * NOUT + krow) * GYN + n] = acc[i];
        }
    }
}

// ---------------- kernel 6: stage2 GEMM with fused y-fold + deapod + |.| ----------------
// M=320 (64-tiles, 80 blocks), N=80, K=237. sA folds stage1 on the fly:
// Af[row][q'] = sum_p i^{r4 p} C1[row][q'+237p]  (coeffs per-block constants)
__global__ void __launch_bounds__(256) gemm2_kernel(float* __restrict__ out) {
    int b  = blockIdx.z;
    int r4 = blockIdx.y;
    int m0 = blockIdx.x * 64;

    __shared__ float2 sA[16][64];
    __shared__ float2 sB[16][80];

    int tid = threadIdx.x;
    int tx = tid & 15, ty = tid >> 4;

    // i^{r4}, i^{2 r4}, i^{3 r4}
    float c1r = (r4 == 0) ? 1.f : (r4 == 2) ? -1.f : 0.f;
    float c1i = (r4 == 1) ? 1.f : (r4 == 3) ? -1.f : 0.f;
    float c2r = (r4 & 1) ? -1.f : 1.f;
    float c3r = (r4 == 0) ? 1.f : (r4 == 2) ? -1.f : 0.f;
    float c3i = (r4 == 3) ? 1.f : (r4 == 1) ? -1.f : 0.f;

    float2 acc[4][5];
#pragma unroll
    for (int i = 0; i < 4; i++)
#pragma unroll
        for (int j = 0; j < 5; j++) acc[i][j] = make_float2(0.f, 0.f);

    const float2* A  = g_stage1 + (size_t)b * NOUT * GYN;   // row stride GYN
    const float2* Bw = g_W2r + r4 * 80 * NQY;

    for (int kk = 0; kk < NQY; kk += 16) {
#pragma unroll
        for (int l = 0; l < 4; l++) {
            int lin = tid + l * 256;
            int kl = lin & 15, ml = lin >> 4;
            int kq = kk + kl;
            float2 v = make_float2(0.f, 0.f);
            if (kq < NQY) {
                const float2* row = A + (size_t)(m0 + ml) * GYN + kq;
                float2 g0 = row[0];
                float2 g1 = row[NQY];
                float2 g2 = row[2 * NQY];
                float2 g3 = row[3 * NQY];
                v.x = g0.x;                 v.y = g0.y;
                v.x = fmaf(c1r, g1.x, v.x); v.x = fmaf(-c1i, g1.y, v.x);
                v.y = fmaf(c1r, g1.y, v.y); v.y = fmaf( c1i, g1.x, v.y);
                v.x = fmaf(c2r, g2.x, v.x);
                v.y = fmaf(c2r, g2.y, v.y);
                v.x = fmaf(c3r, g3.x, v.x); v.x = fmaf(-c3i, g3.y, v.x);
                v.y = fmaf(c3r, g3.y, v.y); v.y = fmaf( c3i, g3.x, v.y);
            }
            sA[kl][ml] = v;
        }
#pragma unroll
        for (int l = 0; l < 5; l++) {
            int lin = tid + l * 256;
            int kl = lin & 15, nl = lin >> 4;
            int kq = kk + kl;
            sB[kl][nl] = (kq < NQY) ? Bw[nl * NQY + kq] : make_float2(0.f, 0.f);
        }
        __syncthreads();
#pragma unroll
        for (int k = 0; k < 16; k++) {
            float2 a[4], bb[5];
#pragma unroll
            for (int i = 0; i < 4; i++) a[i]  = sA[k][i * 16 + ty];
#pragma unroll
            for (int j = 0; j < 5; j++) bb[j] = sB[k][j * 16 + tx];
#pragma unroll
            for (int i = 0; i < 4; i++)
#pragma unroll
                for (int j = 0; j < 5; j++) {
                    acc[i][j].x = fmaf(a[i].x, bb[j].x, acc[i][j].x);
                    acc[i][j].x = fmaf(-a[i].y, bb[j].y, acc[i][j].x);
                    acc[i][j].y = fmaf(a[i].x, bb[j].y, acc[i][j].y);
                    acc[i][j].y = fmaf(a[i].y, bb[j].x, acc[i][j].y);
                }
        }
        __syncthreads();
    }

    float dyv[5];
#pragma unroll
    for (int j = 0; j < 5; j++) dyv[j] = deapod_inv(4 * (j * 16 + tx) + r4, 1.0f / (float)GYN);

    float* ob = out + (size_t)b * NOUT * NOUT;
#pragma unroll
    for (int i = 0; i < 4; i++) {
        int krow = m0 + i * 16 + ty;
        float dxv = deapod_inv(krow, 1.0f / (float)GXN);
#pragma unroll
        for (int j = 0; j < 5; j++) {
            int c_idx = 4 * (j * 16 + tx) + r4;
            float mag = hypotf(acc[i][j].x, acc[i][j].y);
            ob[krow * NOUT + c_idx] = mag * dxv * dyv[j];
        }
    }
}

// ---------------- launch ----------------
extern "C" void kernel_launch(void* const* d_in, const int* in_sizes, int n_in,
                              void* d_out, int out_size) {
    (void)in_sizes; (void)n_in; (void)out_size;
    const float2* ksp   = (const float2*)d_in[0];
    const float*  traj  = (const float*)d_in[1];
    const float*  dcomp = (const float*)d_in[2];
    float* out = (float*)d_out;

    twiddle_kernel<<<319, 256>>>();                                  // W1 + KB + W2r
    zero_kernel<<<9480, 256>>>();                                    // clear + warm L2
    gridding_kernel<<<(NB * NM) / 256, 256>>>(ksp, traj, dcomp);
    fold16_kernel<<<1185, 256>>>();                                  // in-place x-DFT fold
    gemm1_kernel<<<dim3(15, 16, NB), 256>>>();
    gemm2_kernel<<<dim3(5, 4, NB), 256>>>(out);                      // 64-row tiles, fused y-fold
}

// round 17
// speedup vs baseline: 1.0673x; 1.0479x over previous
#include <cuda_runtime.h>

// ---------------- problem constants ----------------
#define GXN  1280
#define GYN  948
#define NB   4
#define NM   262144
#define NOUT 320
#define NQX2 80             // GXN/16
#define NQY  237            // GYN/4
#define KBN  4096           // KB weight table resolution

#define TWO_PI_D 6.28318530717958647692
#define PI_F     3.14159265358979f
#define BETA_F ((float)(3.14159265358979323846 * 4.41021541424))
#define KXC ((float)(1280.0 / TWO_PI_D))
#define KYC ((float)(948.0  / TWO_PI_D))

// ---------------- device scratch ----------------
__device__ float2 g_grid [NB * GXN * GYN];          // 38.8 MB grid; fold16 runs in place
__device__ float2 g_stage1[NB * NOUT * GYN];        // 9.7 MB after x-DFT
__device__ float2 g_foldy[NB * 4 * NOUT * NQY];     // 9.7 MB radix-4 y-folded stage1
__device__ float2 g_W1[NQX2 * 20];                  // stage1 twiddles [q'][t] (c-independent)
__device__ float2 g_W2r[4 * 80 * NQY];              // stage2 twiddles [r4][jc][q'] (scaled)
__device__ float  g_kbtab[KBN + 1];                 // KB weight vs d^2 (16 KB)

// e^{2*pi*i*c/16}, c = 0..15
__device__ __constant__ float2 c_e16[16] = {
    { 1.000000000f,  0.000000000f}, { 0.923879533f,  0.382683432f},
    { 0.707106781f,  0.707106781f}, { 0.382683432f,  0.923879533f},
    { 0.000000000f,  1.000000000f}, {-0.382683432f,  0.923879533f},
    {-0.707106781f,  0.707106781f}, {-0.923879533f,  0.382683432f},
    {-1.000000000f,  0.000000000f}, {-0.923879533f, -0.382683432f},
    {-0.707106781f, -0.707106781f}, {-0.382683432f, -0.923879533f},
    { 0.000000000f, -1.000000000f}, { 0.382683432f, -0.923879533f},
    { 0.707106781f, -0.707106781f}, { 0.923879533f, -0.382683432f}
};

// ---------------- Kaiser-Bessel i0 ----------------
__device__ __forceinline__ float i0f(float x) {
    if (x < 3.75f) {
        float t = x * (1.0f / 3.75f);
        t *= t;
        return 1.0f + t * (3.5156229f + t * (3.0899424f + t * (1.2067492f +
               t * (0.2659732f + t * (0.0360768f + t * 0.0045813f)))));
    } else {
        float inv = 3.75f / x;
        float p = 0.39894228f + inv * (0.01328592f + inv * (0.00225319f +
                  inv * (-0.00157565f + inv * (0.00916281f + inv * (-0.02057706f +
                  inv * (0.02635537f + inv * (-0.01647633f + inv * 0.00392377f)))))));
        return __expf(x) * rsqrtf(x) * p;
    }
}

__device__ __forceinline__ float deapod_inv(int i, float invN) {
    float u = (float)(i - 160) * invN;
    float t = 19.45f - 36.0f * u * u;
    float s = PI_F * sqrtf(t);
    float e = __expf(s);
    float sh = 0.5f * (e - 1.0f / e);
    return s / sh;
}

// ---------------- kernel 1: all twiddles + KB table (one launch) ----------------
__global__ void __launch_bounds__(256) twiddle_kernel() {
    const int T1 = NQX2 * 20;        // 1600  W1
    const int TK = KBN + 1;          // 4097  KB table
    const int T2 = 4 * 80 * NQY;     // 75840 W2r
    int idx = blockIdx.x * 256 + threadIdx.x;
    if (idx < T1) {
        int q = idx / 20, t = idx - q * 20;
        int ph = ((t - 10) * q) % 80; if (ph < 0) ph += 80;
        float sn, cs;
        sincosf((float)(TWO_PI_D / 80.0) * (float)ph, &sn, &cs);
        g_W1[idx] = make_float2(cs, sn);
    } else if (idx < T1 + TK) {
        int i = idx - T1;
        float arg = (float)(KBN - i) * (1.0f / (float)KBN);
        g_kbtab[i] = i0f(BETA_F * sqrtf(fmaxf(arg, 0.0f)));
    } else if (idx < T1 + TK + T2) {
        int i2 = idx - T1 - TK;
        int r4 = i2 / (80 * NQY);
        int rem = i2 - r4 * (80 * NQY);
        int j = rem / NQY, q = rem - j * NQY;
        int k = 4 * j + r4 - 160;
        int ph = (k * q) % GYN; if (ph < 0) ph += GYN;
        float sn, cs;
        sincosf((float)((TWO_PI_D / (double)GYN) * (double)ph), &sn, &cs);
        const float scale = (float)(1.0 / sqrt((double)GXN * (double)GYN));
        g_W2r[i2] = make_float2(cs * scale, sn * scale);
    }
}

// ---------------- kernel 2: zero the grid (also warms L2 for gridding) ----------------
__global__ void __launch_bounds__(256) zero_kernel() {
    float4* p = reinterpret_cast<float4*>(g_grid);
    int idx = blockIdx.x * 256 + threadIdx.x;
    p[idx] = make_float4(0.f, 0.f, 0.f, 0.f);
}

// KB weight via table lookup on d^2
__device__ __forceinline__ float kb_w(float dx) {
    float a = dx * dx * ((float)KBN / 9.0f);
    int   i = (int)a;
    float f = a - (float)i;
    float w0 = g_kbtab[i];
    float w1 = g_kbtab[i + 1];
    return fmaf(w1 - w0, f, w0);
}

// ---------------- kernel 3: KB gridding (v4/v2 vector red atomics) ----------------
__global__ void __launch_bounds__(256) gridding_kernel(const float2* __restrict__ ksp,
                                                       const float*  __restrict__ traj,
                                                       const float*  __restrict__ dcomp) {
    int idx = blockIdx.x * 256 + threadIdx.x;
    int b = idx >> 18;
    int m = idx & (NM - 1);

    float2 kv = ksp[idx];
    float  dc = dcomp[idx];
    float  tx = traj[(size_t)b * 2 * NM + m];
    float  ty = traj[(size_t)b * 2 * NM + NM + m];

    float yre = kv.x * dc, yim = kv.y * dc;
    float gx = tx * KXC, gy = ty * KYC;

    int ix0 = (int)floorf(gx - 3.0f) + 1;
    int iy0 = (int)floorf(gy - 3.0f) + 1;

    float wx[6], wy[6];
    int   xi[6];
#pragma unroll
    for (int j = 0; j < 6; j++) {
        wx[j] = kb_w(gx - (float)(ix0 + j));
        wy[j] = kb_w(gy - (float)(iy0 + j));
        int xm = ix0 + j;
        xm += (xm < 0) ? GXN : 0;
        xm -= (xm >= GXN) ? GXN : 0;
        xi[j] = xm * GYN;
    }

    int iy0m = iy0 % GYN; if (iy0m < 0) iy0m += GYN;
    bool nowrap = (iy0m + 5 < GYN);

    float2* gb = g_grid + (size_t)b * GXN * GYN;

    if (nowrap) {
        bool even = ((iy0m & 1) == 0);
#pragma unroll
        for (int jx = 0; jx < 6; jx++) {
            float wr = wx[jx] * yre;
            float wi = wx[jx] * yim;
            float vr[6], vi[6];
#pragma unroll
            for (int jy = 0; jy < 6; jy++) { vr[jy] = wr * wy[jy]; vi[jy] = wi * wy[jy]; }
            float2* base = gb + xi[jx] + iy0m;
            if (even) {
                asm volatile("red.global.add.v4.f32 [%0], {%1,%2,%3,%4};"
                    :: "l"(__cvta_generic_to_global(base)),     "f"(vr[0]), "f"(vi[0]), "f"(vr[1]), "f"(vi[1]) : "memory");
                asm volatile("red.global.add.v4.f32 [%0], {%1,%2,%3,%4};"
                    :: "l"(__cvta_generic_to_global(base + 2)), "f"(vr[2]), "f"(vi[2]), "f"(vr[3]), "f"(vi[3]) : "memory");
                asm volatile("red.global.add.v4.f32 [%0], {%1,%2,%3,%4};"
                    :: "l"(__cvta_generic_to_global(base + 4)), "f"(vr[4]), "f"(vi[4]), "f"(vr[5]), "f"(vi[5]) : "memory");
            } else {
                asm volatile("red.global.add.v2.f32 [%0], {%1,%2};"
                    :: "l"(__cvta_generic_to_global(base)),     "f"(vr[0]), "f"(vi[0]) : "memory");
                asm volatile("red.global.add.v4.f32 [%0], {%1,%2,%3,%4};"
                    :: "l"(__cvta_generic_to_global(base + 1)), "f"(vr[1]), "f"(vi[1]), "f"(vr[2]), "f"(vi[2]) : "memory");
                asm volatile("red.global.add.v4.f32 [%0], {%1,%2,%3,%4};"
                    :: "l"(__cvta_generic_to_global(base + 3)), "f"(vr[3]), "f"(vi[3]), "f"(vr[4]), "f"(vi[4]) : "memory");
                asm volatile("red.global.add.v2.f32 [%0], {%1,%2};"
                    :: "l"(__cvta_generic_to_global(base + 5)), "f"(vr[5]), "f"(vi[5]) : "memory");
            }
        }
    } else {
        int yi[6];
#pragma unroll
        for (int j = 0; j < 6; j++) {
            int ym = iy0m + j;
            ym -= (ym >= GYN) ? GYN : 0;
            yi[j] = ym;
        }
#pragma unroll
        for (int jx = 0; jx < 6; jx++) {
            float wr = wx[jx] * yre;
            float wi = wx[jx] * yim;
#pragma unroll
            for (int jy = 0; jy < 6; jy++) {
                float vr = wr * wy[jy];
                float vi = wi * wy[jy];
                float2* p = gb + (xi[jx] + yi[jy]);
                asm volatile("red.global.add.v2.f32 [%0], {%1, %2};"
                             :: "l"(__cvta_generic_to_global(p)), "f"(vr), "f"(vi) : "memory");
            }
        }
    }
}

// ---------------- kernel 4: 16-point DFT fold along x (IN PLACE) + twist ----------------
__global__ void __launch_bounds__(256) fold16_kernel() {
    int idx = blockIdx.x * 256 + threadIdx.x;      // NB*80*948 = 303,360 = 1185*256
    int b = idx / (NQX2 * GYN);
    int rem = idx - b * (NQX2 * GYN);
    int q = rem / GYN;
    int y = rem - q * GYN;

    float2* gb = g_grid + (size_t)b * GXN * GYN + (size_t)q * GYN + y;
    float2 g[16];
#pragma unroll
    for (int m = 0; m < 16; m++) g[m] = gb[(size_t)m * NQX2 * GYN];

    float2 A[16];
#pragma unroll
    for (int j = 0; j < 4; j++) {
        float2 i0 = g[j], i1 = g[j + 4], i2 = g[j + 8], i3 = g[j + 12];
        A[0 * 4 + j] = make_float2(i0.x + i1.x + i2.x + i3.x, i0.y + i1.y + i2.y + i3.y);
        A[1 * 4 + j] = make_float2(i0.x - i1.y - i2.x + i3.y, i0.y + i1.x - i2.y - i3.x);
        A[2 * 4 + j] = make_float2(i0.x - i1.x + i2.x - i3.x, i0.y - i1.y + i2.y - i3.y);
        A[3 * 4 + j] = make_float2(i0.x + i1.y - i2.x - i3.y, i0.y - i1.x - i2.y + i3.x);
    }

    float sw, cw;
    sincosf((float)(TWO_PI_D / 1280.0) * (float)q, &sw, &cw);
    float twr = 1.0f, twi = 0.0f;

#pragma unroll
    for (int c = 0; c < 16; c++) {
        int r4 = c & 3;
        float2 a0 = A[r4 * 4 + 0], a1 = A[r4 * 4 + 1], a2 = A[r4 * 4 + 2], a3 = A[r4 * 4 + 3];
        float2 w1 = c_e16[c], w2 = c_e16[(2 * c) & 15], w3 = c_e16[(3 * c) & 15];
        float xr = a0.x, xi = a0.y;
        xr = fmaf(w1.x, a1.x, xr); xr = fmaf(-w1.y, a1.y, xr);
        xi = fmaf(w1.x, a1.y, xi); xi = fmaf( w1.y, a1.x, xi);
        xr = fmaf(w2.x, a2.x, xr); xr = fmaf(-w2.y, a2.y, xr);
        xi = fmaf(w2.x, a2.y, xi); xi = fmaf( w2.y, a2.x, xi);
        xr = fmaf(w3.x, a3.x, xr); xr = fmaf(-w3.y, a3.y, xr);
        xi = fmaf(w3.x, a3.y, xi); xi = fmaf( w3.y, a3.x, xi);
        float fr = twr * xr - twi * xi;
        float fi = twr * xi + twi * xr;
        gb[(size_t)c * NQX2 * GYN] = make_float2(fr, fi);
        float ntr = twr * cw - twi * sw;
        twi = twr * sw + twi * cw;
        twr = ntr;
    }
}

// ---------------- kernel 5: stage1 GEMM, TWO c-planes per block (shared W panel) ----------------
// For cp in [0,8): processes c0 = cp and c1 = cp+8.  M=20, N=948 (64-tiles), K=80.
// Per k-step: 5 LDS(a, shared) + 2 LDS(b) feed 40 FMAs.
__global__ void __launch_bounds__(256) gemm1_kernel() {
    int b  = blockIdx.z;
    int cp = blockIdx.y;          // 0..7
    int n0 = blockIdx.x * 64;
    int c0 = cp, c1 = cp + 8;

    __shared__ float2 sA [16][20];
    __shared__ float2 sB0[16][64];
    __shared__ float2 sB1[16][64];

    int tid = threadIdx.x;
    int tx = tid & 63, ty = tid >> 6;

    float2 acc0[5], acc1[5];
#pragma unroll
    for (int i = 0; i < 5; i++) {
        acc0[i] = make_float2(0.f, 0.f);
        acc1[i] = make_float2(0.f, 0.f);
    }

    const float2* F0 = g_grid + (size_t)b * GXN * GYN + (size_t)c0 * NQX2 * GYN;
    const float2* F1 = g_grid + (size_t)b * GXN * GYN + (size_t)c1 * NQX2 * GYN;

    for (int kk = 0; kk < NQX2; kk += 16) {
#pragma unroll
        for (int l = 0; l < 2; l++) {
            int lin = tid + l * 256;
            if (lin < 320) {
                int kl = lin / 20, tl = lin - kl * 20;
                sA[kl][tl] = g_W1[(kk + kl) * 20 + tl];
            }
        }
#pragma unroll
        for (int l = 0; l < 4; l++) {
            int lin = tid + l * 256;
            int nl = lin & 63, kl = lin >> 6;
            int n = n0 + nl;
            size_t off = (size_t)(kk + kl) * GYN + n;
            bool ok = (n < GYN);
            sB0[kl][nl] = ok ? F0[off] : make_float2(0.f, 0.f);
            sB1[kl][nl] = ok ? F1[off] : make_float2(0.f, 0.f);
        }
        __syncthreads();
#pragma unroll
        for (int k2 = 0; k2 < 16; k2++) {
            float2 b0 = sB0[k2][tx];
            float2 b1 = sB1[k2][tx];
#pragma unroll
            for (int i = 0; i < 5; i++) {
                float2 a = sA[k2][ty * 5 + i];
                acc0[i].x = fmaf(a.x, b0.x, acc0[i].x);
                acc0[i].x = fmaf(-a.y, b0.y, acc0[i].x);
                acc0[i].y = fmaf(a.x, b0.y, acc0[i].y);
                acc0[i].y = fmaf(a.y, b0.x, acc0[i].y);
                acc1[i].x = fmaf(a.x, b1.x, acc1[i].x);
                acc1[i].x = fmaf(-a.y, b1.y, acc1[i].x);
                acc1[i].y = fmaf(a.x, b1.y, acc1[i].y);
                acc1[i].y = fmaf(a.y, b1.x, acc1[i].y);
            }
        }
        __syncthreads();
    }

    int n = n0 + tx;
    if (n < GYN) {
#pragma unroll
        for (int i = 0; i < 5; i++) {
            int t = ty * 5 + i;
            g_stage1[((size_t)b * NOUT + (16 * t + c0)) * GYN + n] = acc0[i];
            g_stage1[((size_t)b * NOUT + (16 * t + c1)) * GYN + n] = acc1[i];
        }
    }
}

// ---------------- kernel 6: radix-4 fold along y ----------------
__global__ void __launch_bounds__(256) foldy_kernel() {
    int idx = blockIdx.x * 256 + threadIdx.x;
    if (idx >= NB * NOUT * NQY) return;
    int b = idx / (NOUT * NQY);
    int rem = idx - b * (NOUT * NQY);
    int k = rem / NQY;
    int q = rem - k * NQY;

    const float2* cb = g_stage1 + ((size_t)b * NOUT + k) * GYN + q;
    float2 g0 = cb[0];
    float2 g1 = cb[NQY];
    float2 g2 = cb[2 * NQY];
    float2 g3 = cb[3 * NQY];

    float2 s0 = make_float2(g0.x + g1.x + g2.x + g3.x, g0.y + g1.y + g2.y + g3.y);
    float2 s1 = make_float2(g0.x - g1.y - g2.x + g3.y, g0.y + g1.x - g2.y - g3.x);
    float2 s2 = make_float2(g0.x - g1.x + g2.x - g3.x, g0.y - g1.y + g2.y - g3.y);
    float2 s3 = make_float2(g0.x + g1.y - g2.x - g3.y, g0.y - g1.x - g2.y + g3.x);

    size_t plane = (size_t)NOUT * NQY;
    size_t base = ((size_t)b * 4) * plane + (size_t)k * NQY + q;
    g_foldy[base]             = s0;
    g_foldy[base + plane]     = s1;
    g_foldy[base + 2 * plane] = s2;
    g_foldy[base + 3 * plane] = s3;
}

// ---------------- kernel 7: stage2 GEMM + deapod + |.| (R14 64-tile shape) ----------------
__global__ void __launch_bounds__(256) gemm2_kernel(float* __restrict__ out) {
    int b  = blockIdx.z;
    int r4 = blockIdx.y;
    int m0 = blockIdx.x * 64;

    __shared__ float2 sA[16][64];
    __shared__ float2 sB[16][80];

    int tid = threadIdx.x;
    int tx = tid & 15, ty = tid >> 4;

    float2 acc[4][5];
#pragma unroll
    for (int i = 0; i < 4; i++)
#pragma unroll
        for (int j = 0; j < 5; j++) acc[i][j] = make_float2(0.f, 0.f);

    const float2* A  = g_foldy + ((size_t)(b * 4 + r4)) * NOUT * NQY;
    const float2* Bw = g_W2r + r4 * 80 * NQY;

    for (int kk = 0; kk < NQY; kk += 16) {
#pragma unroll
        for (int l = 0; l < 4; l++) {
            int lin = tid + l * 256;
            int kl = lin & 15, ml = lin >> 4;
            int kq = kk + kl;
            sA[kl][ml] = (kq < NQY) ? A[(size_t)(m0 + ml) * NQY + kq] : make_float2(0.f, 0.f);
        }
#pragma unroll
        for (int l = 0; l < 5; l++) {
            int lin = tid + l * 256;
            int kl = lin & 15, nl = lin >> 4;
            int kq = kk + kl;
            sB[kl][nl] = (kq < NQY) ? Bw[nl * NQY + kq] : make_float2(0.f, 0.f);
        }
        __syncthreads();
#pragma unroll
        for (int k = 0; k < 16; k++) {
            float2 a[4], bb[5];
#pragma unroll
            for (int i = 0; i < 4; i++) a[i]  = sA[k][i * 16 + ty];
#pragma unroll
            for (int j = 0; j < 5; j++) bb[j] = sB[k][j * 16 + tx];
#pragma unroll
            for (int i = 0; i < 4; i++)
#pragma unroll
                for (int j = 0; j < 5; j++) {
                    acc[i][j].x = fmaf(a[i].x, bb[j].x, acc[i][j].x);
                    acc[i][j].x = fmaf(-a[i].y, bb[j].y, acc[i][j].x);
                    acc[i][j].y = fmaf(a[i].x, bb[j].y, acc[i][j].y);
                    acc[i][j].y = fmaf(a[i].y, bb[j].x, acc[i][j].y);
                }
        }
        __syncthreads();
    }

    float dyv[5];
#pragma unroll
    for (int j = 0; j < 5; j++) dyv[j] = deapod_inv(4 * (j * 16 + tx) + r4, 1.0f / (float)GYN);

    float* ob = out + (size_t)b * NOUT * NOUT;
#pragma unroll
    for (int i = 0; i < 4; i++) {
        int krow = m0 + i * 16 + ty;
        float dxv = deapod_inv(krow, 1.0f / (float)GXN);
#pragma unroll
        for (int j = 0; j < 5; j++) {
            int c_idx = 4 * (j * 16 + tx) + r4;
            float mag = hypotf(acc[i][j].x, acc[i][j].y);
            ob[krow * NOUT + c_idx] = mag * dxv * dyv[j];
        }
    }
}

// ---------------- launch ----------------
extern "C" void kernel_launch(void* const* d_in, const int* in_sizes, int n_in,
                              void* d_out, int out_size) {
    (void)in_sizes; (void)n_in; (void)out_size;
    const float2* ksp   = (const float2*)d_in[0];
    const float*  traj  = (const float*)d_in[1];
    const float*  dcomp = (const float*)d_in[2];
    float* out = (float*)d_out;

    twiddle_kernel<<<319, 256>>>();                                  // W1 + KB + W2r
    zero_kernel<<<9480, 256>>>();                                    // clear + warm L2
    gridding_kernel<<<(NB * NM) / 256, 256>>>(ksp, traj, dcomp);
    fold16_kernel<<<1185, 256>>>();                                  // in-place x-DFT fold
    gemm1_kernel<<<dim3(15, 8, NB), 256>>>();                        // 480 blocks, 2 c-planes each
    foldy_kernel<<<1185, 256>>>();
    gemm2_kernel<<<dim3(5, 4, NB), 256>>>(out);                      // 64-row tiles (R14)
}